// round 14
// baseline (speedup 1.0000x reference)
#include <cuda_runtime.h>
#include <cuda_bf16.h>
#include <cstdint>

// ============================ helpers ======================================
__device__ __forceinline__ uint32_t smem_u32(const void* p) {
    uint32_t a;
    asm("{ .reg .u64 t; cvta.to.shared.u64 t, %1; cvt.u32.u64 %0, t; }" : "=r"(a) : "l"(p));
    return a;
}
__device__ __forceinline__ void ldsm_x4(uint32_t* r, uint32_t addr) {
    asm volatile("ldmatrix.sync.aligned.m8n8.x4.shared.b16 {%0,%1,%2,%3}, [%4];"
                 : "=r"(r[0]), "=r"(r[1]), "=r"(r[2]), "=r"(r[3]) : "r"(addr));
}
__device__ __forceinline__ void mma_bf16(float* c, const uint32_t* a, const uint32_t* b) {
    asm volatile("mma.sync.aligned.m16n8k16.row.col.f32.bf16.bf16.f32 "
                 "{%0,%1,%2,%3}, {%4,%5,%6,%7}, {%8,%9}, {%0,%1,%2,%3};"
                 : "+f"(c[0]), "+f"(c[1]), "+f"(c[2]), "+f"(c[3])
                 : "r"(a[0]), "r"(a[1]), "r"(a[2]), "r"(a[3]), "r"(b[0]), "r"(b[1]));
}
__device__ __forceinline__ void cpa16(uint32_t s, const void* g) {
    asm volatile("cp.async.ca.shared.global [%0], [%1], 16;" :: "r"(s), "l"(g));
}
#define CP_COMMIT() asm volatile("cp.async.commit_group;" ::: "memory")
#define CP_WAIT0()  asm volatile("cp.async.wait_group 0;" ::: "memory")
#define SWZ(o) ((o) ^ (((o) >> 3) & 0x70))

__device__ __forceinline__ float fsig(float x) {
    return __fdividef(1.f, 1.f + __expf(-x));
}
__device__ __forceinline__ float ftanh(float x) {
    return 2.f * __fdividef(1.f, 1.f + __expf(-2.f * x)) - 1.f;
}

// ============================ scratch ======================================
__device__ float         g_W12[256 * 128];
__device__ float         g_b1w2[128];
__device__ float         g_rowsum[8192];
__device__ __nv_bfloat16 g_Bhi[128 * 8192];
__device__ __nv_bfloat16 g_Blo[128 * 8192];
__device__ __nv_bfloat16 g_Bhi2[128 * 8192];
__device__ __nv_bfloat16 g_Blo2[128 * 8192];
__device__ float         g_seqs[4096 * 128];
__device__ float         g_spart[2 * 4096 * 128];
__device__ float         g_xp[2 * 4096 * 512];
__device__ float         g_WT[4 * 128 * 512];
__device__ float         g_bias2[2 * 512];
__device__ int           g_idx5[2 * 4096];
__device__ float         g_hfinal[2 * 64 * 128];

// =================== pipelined mma.sync split-bf16 GEMM ====================
// C[M,128-slice] = gatherRows(A)[M,K-chunk](fp32) @ B[K-chunk,n-slice]
// (B hi/lo [128][8192] bf16). CTA tile 64 x BN, K-tile 64, 256 threads,
// 2-stage cp.async. grid = (M/64 m, 128/BN n, ksplit); C += z*zoff.
// If hi_out != null (BN=128 only): epilogue writes transposed hi/lo bf16.
template<int BN, int NIT>
__global__ __launch_bounds__(256, 1)
void gemm_mma_kernel(const float* __restrict__ A,
                     const __nv_bfloat16* __restrict__ Bhi,
                     const __nv_bfloat16* __restrict__ Blo,
                     float* __restrict__ C,
                     const int* __restrict__ row_idx,
                     float* __restrict__ rowsum_out,
                     __nv_bfloat16* __restrict__ hi_out,
                     __nv_bfloat16* __restrict__ lo_out,
                     long zoff)
{
    constexpr int STAGE   = 16384 + BN * 256;
    constexpr int BLO_OFF = 16384 + BN * 128;
    constexpr int NF      = BN / 32;
    constexpr int PG      = NF / 2;
    constexpr int T       = 256 / BN;
    constexpr int BCH     = 8 / T;

    extern __shared__ char dsm[];
    __shared__ int sidx[64];

    const int tid = threadIdx.x;
    const int w = tid >> 5, l = tid & 31;
    const int m0 = blockIdx.x * 64;
    const int n0 = blockIdx.y * BN;
    const int k0 = blockIdx.z * NIT * 64;
    C += (long)blockIdx.z * zoff;

    if (tid < 64) sidx[tid] = row_idx ? row_idx[m0 + tid] : (m0 + tid);
    __syncthreads();

    const uint32_t dyn = smem_u32(dsm);
    const uint32_t tb0 = (dyn + 1023u) & ~1023u;
    char* const tptr = dsm + (tb0 - dyn);

    const int ar = tid >> 2, aq = tid & 3;
    const float* Ap = A + (long)sidx[ar] * 8192 + k0 + aq * 16;
    const uint32_t aswz0 = SWZ((uint32_t)(ar * 128 + aq * 32));
    const uint32_t aswz1 = SWZ((uint32_t)(ar * 128 + aq * 32 + 16));

    const int rb = tid / T, sub = tid % T;
    const __nv_bfloat16* Bhp = Bhi + (long)(n0 + rb) * 8192 + k0 + sub * (64 / T);
    const __nv_bfloat16* Blp = Blo + (long)(n0 + rb) * 8192 + k0 + sub * (64 / T);
    uint32_t bswz[BCH];
    #pragma unroll
    for (int i = 0; i < BCH; i++)
        bswz[i] = SWZ((uint32_t)(rb * 128 + sub * (128 / T) + i * 16));

    const int mw = (w & 1) * 32, nw = (w >> 1) * (BN / 4);
    uint32_t aLin[2], aMask[2];
    #pragma unroll
    for (int im = 0; im < 2; im++) {
        uint32_t lin = (uint32_t)((mw + 16 * im + (l & 15)) * 128 + (l >> 4) * 16);
        aLin[im] = lin;
        aMask[im] = (lin >> 3) & 0x70;
    }
    uint32_t bLin[PG], bMask[PG];
    #pragma unroll
    for (int pg = 0; pg < PG; pg++) {
        uint32_t n = (uint32_t)(nw + (pg * 2 + (l >> 4)) * 8 + (l & 7));
        uint32_t lin = n * 128 + ((l >> 3) & 1) * 16;
        bLin[pg] = lin;
        bMask[pg] = (lin >> 3) & 0x70;
    }

    float acc[2][NF][4];
    #pragma unroll
    for (int im = 0; im < 2; im++)
        #pragma unroll
        for (int jn = 0; jn < NF; jn++)
            #pragma unroll
            for (int e = 0; e < 4; e++) acc[im][jn][e] = 0.f;

    float racc = 0.f;
    const bool do_rs = (rowsum_out != nullptr) && (blockIdx.y == 0);

    float4 av[4];
    #pragma unroll
    for (int i = 0; i < 4; i++) av[i] = *(const float4*)(Ap + i * 4);
    #pragma unroll
    for (int i = 0; i < BCH; i++) {
        cpa16(tb0 + 16384   + bswz[i], (const char*)Bhp + i * 16);
        cpa16(tb0 + BLO_OFF + bswz[i], (const char*)Blp + i * 16);
    }
    CP_COMMIT();

    for (int it = 0; it < NIT; it++) {
        const int s = it & 1;
        char* const sp = tptr + s * STAGE;

        {
            float vv[16] = { av[0].x, av[0].y, av[0].z, av[0].w,
                             av[1].x, av[1].y, av[1].z, av[1].w,
                             av[2].x, av[2].y, av[2].z, av[2].w,
                             av[3].x, av[3].y, av[3].z, av[3].w };
            uint32_t hu[8], lu[8];
            #pragma unroll
            for (int p = 0; p < 8; p++) {
                float x = vv[2 * p], y = vv[2 * p + 1];
                __nv_bfloat16 hx = __float2bfloat16(x);
                __nv_bfloat16 hy = __float2bfloat16(y);
                __nv_bfloat16 lx = __float2bfloat16(x - __bfloat162float(hx));
                __nv_bfloat16 ly = __float2bfloat16(y - __bfloat162float(hy));
                hu[p] = (uint32_t)__bfloat16_as_ushort(hx) |
                        ((uint32_t)__bfloat16_as_ushort(hy) << 16);
                lu[p] = (uint32_t)__bfloat16_as_ushort(lx) |
                        ((uint32_t)__bfloat16_as_ushort(ly) << 16);
            }
            if (do_rs) {
                float sacc = 0.f;
                #pragma unroll
                for (int p = 0; p < 16; p++) sacc += vv[p];
                racc += sacc;
            }
            *(uint4*)(sp +        aswz0) = make_uint4(hu[0], hu[1], hu[2], hu[3]);
            *(uint4*)(sp +        aswz1) = make_uint4(hu[4], hu[5], hu[6], hu[7]);
            *(uint4*)(sp + 8192 + aswz0) = make_uint4(lu[0], lu[1], lu[2], lu[3]);
            *(uint4*)(sp + 8192 + aswz1) = make_uint4(lu[4], lu[5], lu[6], lu[7]);
        }
        if (it + 1 < NIT) {
            const int kt = (it + 1) * 64;
            #pragma unroll
            for (int i = 0; i < 4; i++) av[i] = *(const float4*)(Ap + kt + i * 4);
        }

        CP_WAIT0();
        __syncthreads();

        if (it + 1 < NIT) {
            const int kt = (it + 1) * 64;
            const uint32_t db = tb0 + (s ^ 1) * STAGE;
            #pragma unroll
            for (int i = 0; i < BCH; i++) {
                cpa16(db + 16384   + bswz[i], (const char*)(Bhp + kt) + i * 16);
                cpa16(db + BLO_OFF + bswz[i], (const char*)(Blp + kt) + i * 16);
            }
            CP_COMMIT();
        }

        const uint32_t cb = tb0 + s * STAGE;
        #pragma unroll
        for (int ks = 0; ks < 4; ks++) {
            const uint32_t kb = ks * 32;
            uint32_t ah[2][4], al[2][4], bh[NF][2], bl[NF][2];
            #pragma unroll
            for (int im = 0; im < 2; im++) {
                uint32_t off = (aLin[im] + kb) ^ aMask[im];
                ldsm_x4(ah[im], cb + off);
                ldsm_x4(al[im], cb + 8192 + off);
            }
            #pragma unroll
            for (int pg = 0; pg < PG; pg++) {
                uint32_t off = (bLin[pg] + kb) ^ bMask[pg];
                uint32_t t4[4];
                ldsm_x4(t4, cb + 16384 + off);
                bh[pg * 2][0] = t4[0]; bh[pg * 2][1] = t4[1];
                bh[pg * 2 + 1][0] = t4[2]; bh[pg * 2 + 1][1] = t4[3];
                ldsm_x4(t4, cb + BLO_OFF + off);
                bl[pg * 2][0] = t4[0]; bl[pg * 2][1] = t4[1];
                bl[pg * 2 + 1][0] = t4[2]; bl[pg * 2 + 1][1] = t4[3];
            }
            #pragma unroll
            for (int im = 0; im < 2; im++)
                #pragma unroll
                for (int jn = 0; jn < NF; jn++) {
                    mma_bf16(acc[im][jn], ah[im], bh[jn]);
                    mma_bf16(acc[im][jn], ah[im], bl[jn]);
                    mma_bf16(acc[im][jn], al[im], bh[jn]);
                }
        }
    }

    if (do_rs) {
        racc += __shfl_xor_sync(0xffffffffu, racc, 1);
        racc += __shfl_xor_sync(0xffffffffu, racc, 2);
        if (aq == 0) rowsum_out[m0 + ar] = racc;
    }

    const int g = l >> 2, q = l & 3;
    if (BN == 128 && hi_out) {
        __syncthreads();
        #pragma unroll
        for (int im = 0; im < 2; im++) {
            const int rl0 = mw + 16 * im + g;
            const int rl1 = rl0 + 8;
            #pragma unroll
            for (int jn = 0; jn < NF; jn++) {
                const int col = nw + 8 * jn + 2 * q;
                float vs[4] = { acc[im][jn][0], acc[im][jn][1],
                                acc[im][jn][2], acc[im][jn][3] };
                int rr[4] = { rl0, rl0, rl1, rl1 };
                int cc[4] = { col, col + 1, col, col + 1 };
                #pragma unroll
                for (int e = 0; e < 4; e++) {
                    __nv_bfloat16 h = __float2bfloat16(vs[e]);
                    __nv_bfloat16 lo = __float2bfloat16(vs[e] - __bfloat162float(h));
                    *(__nv_bfloat16*)(tptr + cc[e] * 144 + rr[e] * 2) = h;
                    *(__nv_bfloat16*)(tptr + 18432 + cc[e] * 144 + rr[e] * 2) = lo;
                }
            }
        }
        __syncthreads();
        #pragma unroll
        for (int i = 0; i < 4; i++) {
            int u = tid + 256 * i;
            int n = u >> 3, c = u & 7;
            *(uint4*)(hi_out + (long)n * 8192 + m0 + c * 8) =
                *(const uint4*)(tptr + n * 144 + c * 16);
            *(uint4*)(lo_out + (long)n * 8192 + m0 + c * 8) =
                *(const uint4*)(tptr + 18432 + n * 144 + c * 16);
        }
    } else {
        #pragma unroll
        for (int im = 0; im < 2; im++) {
            const int rl0 = mw + 16 * im + g;
            const int rl1 = rl0 + 8;
            #pragma unroll
            for (int jn = 0; jn < NF; jn++) {
                const int col = n0 + nw + 8 * jn + 2 * q;
                float* p0 = C + (long)(m0 + rl0) * 128 + col;
                float* p1 = C + (long)(m0 + rl1) * 128 + col;
                *(float2*)p0 = make_float2(acc[im][jn][0], acc[im][jn][1]);
                *(float2*)p1 = make_float2(acc[im][jn][2], acc[im][jn][3]);
            }
        }
    }
}

// ======= Y0 GEMM with fused transpose + hi/lo split epilogue ===============
// Bhi/Blo[128][8192] <- split(X[8192,256] @ W12[256,128]); CTA = 32 rows.
__global__ __launch_bounds__(256)
void y0split_kernel(const float* __restrict__ X, const float* __restrict__ W12,
                    __nv_bfloat16* __restrict__ hi, __nv_bfloat16* __restrict__ lo)
{
    constexpr int BK = 16;
    __shared__ float As[BK][36];
    __shared__ float Bs[BK][128];
    __shared__ __nv_bfloat16 sh[128][40];
    __shared__ __nv_bfloat16 sl[128][40];

    const int tid = threadIdx.x;
    const int tx = tid & 15, ty = tid >> 4;
    const int m0 = blockIdx.y * 32;

    const int lr = tid >> 3, lc4 = tid & 7;      // 32 rows x 8 float4 = 256 thr
    const float* Ap = X + (long)(m0 + lr) * 256 + lc4 * 4;
    const int kb0 = tid >> 5, kc0 = tid & 31;
    const float* Bp0 = W12 + (long)kb0 * 128 + kc0 * 4;
    const float* Bp1 = W12 + (long)(kb0 + 8) * 128 + kc0 * 4;

    float acc[2][8];
    #pragma unroll
    for (int i = 0; i < 2; i++)
        #pragma unroll
        for (int j = 0; j < 8; j++) acc[i][j] = 0.f;

    // A tile covers 32 rows x 32 cols (2 x BK) per double-load; simpler: load
    // BK=16 cols per iter with 128 active threads (lr<32, lc4<4).
    const bool aAct = (lc4 < 4);
    const float* Ap2 = X + (long)(m0 + lr) * 256 + (lc4 & 3) * 4;

    float4 av = make_float4(0.f, 0.f, 0.f, 0.f);
    if (aAct) av = *(const float4*)Ap2;
    float4 bv0 = *(const float4*)Bp0;
    float4 bv1 = *(const float4*)Bp1;

    for (int kt = 0; kt < 256; kt += BK) {
        __syncthreads();
        if (aAct) {
            int c0 = (lc4 & 3) * 4;
            As[c0 + 0][lr] = av.x; As[c0 + 1][lr] = av.y;
            As[c0 + 2][lr] = av.z; As[c0 + 3][lr] = av.w;
        }
        *(float4*)&Bs[kb0][kc0 * 4]     = bv0;
        *(float4*)&Bs[kb0 + 8][kc0 * 4] = bv1;
        __syncthreads();
        if (kt + BK < 256) {
            if (aAct) av = *(const float4*)(Ap2 + kt + BK);
            bv0 = *(const float4*)(Bp0 + (long)(kt + BK) * 128);
            bv1 = *(const float4*)(Bp1 + (long)(kt + BK) * 128);
        }
        #pragma unroll
        for (int k = 0; k < BK; k++) {
            float a0 = As[k][ty * 2], a1 = As[k][ty * 2 + 1];
            float4 b0 = *(const float4*)&Bs[k][tx * 8];
            float4 b1 = *(const float4*)&Bs[k][tx * 8 + 4];
            acc[0][0] += a0 * b0.x; acc[0][1] += a0 * b0.y;
            acc[0][2] += a0 * b0.z; acc[0][3] += a0 * b0.w;
            acc[0][4] += a0 * b1.x; acc[0][5] += a0 * b1.y;
            acc[0][6] += a0 * b1.z; acc[0][7] += a0 * b1.w;
            acc[1][0] += a1 * b0.x; acc[1][1] += a1 * b0.y;
            acc[1][2] += a1 * b0.z; acc[1][3] += a1 * b0.w;
            acc[1][4] += a1 * b1.x; acc[1][5] += a1 * b1.y;
            acc[1][6] += a1 * b1.z; acc[1][7] += a1 * b1.w;
        }
    }
    __syncthreads();
    #pragma unroll
    for (int i = 0; i < 2; i++) {
        int row = ty * 2 + i;
        #pragma unroll
        for (int j = 0; j < 8; j++) {
            int col = tx * 8 + j;
            float v = acc[i][j];
            __nv_bfloat16 h = __float2bfloat16(v);
            sh[col][row] = h;
            sl[col][row] = __float2bfloat16(v - __bfloat162float(h));
        }
    }
    __syncthreads();
    #pragma unroll
    for (int i = 0; i < 2; i++) {
        int u = tid + 256 * i;        // 512 uint4 per array
        int n = u >> 2, c = u & 3;
        *(uint4*)(hi + (long)n * 8192 + m0 + c * 8) = *(const uint4*)&sh[n][c * 8];
        *(uint4*)(lo + (long)n * 8192 + m0 + c * 8) = *(const uint4*)&sl[n][c * 8];
    }
}

// =============== split-K(2) reduce + bias for seqs =========================
__global__ __launch_bounds__(256)
void reduce_seqs_kernel(const float* __restrict__ part, const int* __restrict__ tok,
                        const float* __restrict__ rowsum, const float* __restrict__ b2,
                        const float* __restrict__ b1w2, float* __restrict__ seqs)
{
    int f = blockIdx.x * 256 + threadIdx.x;
    int r = f >> 5, c4 = f & 31;
    float4 a = ((const float4*)part)[f];
    float4 b = ((const float4*)(part + 524288))[f];
    float rs = rowsum[tok[r]];
    float4 bb = ((const float4*)b2)[c4];
    float4 vv = ((const float4*)b1w2)[c4];
    float4 o;
    o.x = a.x + b.x + bb.x + rs * vv.x;
    o.y = a.y + b.y + bb.y + rs * vv.y;
    o.z = a.z + b.z + bb.z + rs * vv.z;
    o.w = a.w + b.w + bb.w + rs * vv.w;
    ((float4*)seqs)[f] = o;
}

// =============== fp32 tiled GEMM (xp; z-merged) ============================
template<int BM, int MR>
__launch_bounds__(256)
__global__ void gemm128_kernel(const float* __restrict__ A, const float* __restrict__ B,
                               float* __restrict__ C, int M, int N, int K,
                               const int* __restrict__ row_idx,
                               const float* __restrict__ bias,
                               long bOff, int idxOff, long cOff, int biasOff)
{
    constexpr int BK  = 16;
    constexpr int PAD = BM + 4;
    __shared__ float As[BK][PAD];
    __shared__ float Bs[BK][128];
    __shared__ int   sidx[BM];

    B += (long)blockIdx.z * bOff;
    C += (long)blockIdx.z * cOff;
    if (row_idx) row_idx += blockIdx.z * idxOff;
    if (bias)    bias    += blockIdx.z * biasOff;

    const int tid = threadIdx.x;
    const int tx = tid & 15, ty = tid >> 4;
    const int m0 = blockIdx.y * BM, n0 = blockIdx.x * 128;

    if (row_idx && tid < BM) sidx[tid] = row_idx[m0 + tid];
    __syncthreads();

    const int aThreads = BM * 4;
    const int lr = tid >> 2, lc4 = tid & 3;
    const float* Ap = nullptr;
    if (tid < aThreads) {
        int arr = row_idx ? sidx[lr] : (m0 + lr);
        Ap = A + (long)arr * K + lc4 * 4;
    }
    const int kb0 = tid >> 5, kc0 = tid & 31;
    const float* Bp0 = B + (long)kb0 * N + n0 + kc0 * 4;
    const float* Bp1 = B + (long)(kb0 + 8) * N + n0 + kc0 * 4;

    float acc[MR][8];
    #pragma unroll
    for (int i = 0; i < MR; i++)
        #pragma unroll
        for (int j = 0; j < 8; j++) acc[i][j] = 0.f;

    float4 av = make_float4(0.f, 0.f, 0.f, 0.f);
    if (tid < aThreads) av = *(const float4*)Ap;
    float4 bv0 = *(const float4*)Bp0;
    float4 bv1 = *(const float4*)Bp1;

    for (int kt = 0; kt < K; kt += BK) {
        __syncthreads();
        if (tid < aThreads) {
            As[lc4 * 4 + 0][lr] = av.x; As[lc4 * 4 + 1][lr] = av.y;
            As[lc4 * 4 + 2][lr] = av.z; As[lc4 * 4 + 3][lr] = av.w;
        }
        *(float4*)&Bs[kb0][kc0 * 4]     = bv0;
        *(float4*)&Bs[kb0 + 8][kc0 * 4] = bv1;
        __syncthreads();
        if (kt + BK < K) {
            if (tid < aThreads) av = *(const float4*)(Ap + kt + BK);
            bv0 = *(const float4*)(Bp0 + (long)(kt + BK) * N);
            bv1 = *(const float4*)(Bp1 + (long)(kt + BK) * N);
        }
        #pragma unroll
        for (int k = 0; k < BK; k++) {
            float a[MR];
            #pragma unroll
            for (int i = 0; i < MR; i++) a[i] = As[k][ty * MR + i];
            float4 b0 = *(const float4*)&Bs[k][tx * 8];
            float4 b1 = *(const float4*)&Bs[k][tx * 8 + 4];
            #pragma unroll
            for (int i = 0; i < MR; i++) {
                acc[i][0] += a[i] * b0.x; acc[i][1] += a[i] * b0.y;
                acc[i][2] += a[i] * b0.z; acc[i][3] += a[i] * b0.w;
                acc[i][4] += a[i] * b1.x; acc[i][5] += a[i] * b1.y;
                acc[i][6] += a[i] * b1.z; acc[i][7] += a[i] * b1.w;
            }
        }
    }
    float addc[8];
    #pragma unroll
    for (int j = 0; j < 8; j++) addc[j] = bias ? bias[n0 + tx * 8 + j] : 0.f;
    #pragma unroll
    for (int i = 0; i < MR; i++) {
        int rr = ty * MR + i;
        float* crow = C + (long)(m0 + rr) * N + n0 + tx * 8;
        *(float4*)(crow)     = make_float4(acc[i][0] + addc[0], acc[i][1] + addc[1],
                                           acc[i][2] + addc[2], acc[i][3] + addc[3]);
        *(float4*)(crow + 4) = make_float4(acc[i][4] + addc[4], acc[i][5] + addc[5],
                                           acc[i][6] + addc[6], acc[i][7] + addc[7]);
    }
}

// =============== fused prep: w12 | b1w2 | idx5 | transpose4 | bias concat ==
__global__ void prep_kernel(const float* __restrict__ W1, const float* __restrict__ W2,
                            float* __restrict__ W12,
                            const float* __restrict__ b1, float* __restrict__ b1w2,
                            int* __restrict__ idx5,
                            const float* __restrict__ s0, const float* __restrict__ s1,
                            const float* __restrict__ s2, const float* __restrict__ s3,
                            float* __restrict__ WT,
                            const float* __restrict__ bf, const float* __restrict__ bb,
                            float* __restrict__ bias2)
{
    const int bx = blockIdx.x;
    const int tid = threadIdx.x;
    if (bx < 128) {                         // W12 = W1@W2
        int idx = bx * 256 + tid;
        int d = idx >> 7, n = idx & 127;
        float acc = 0.f;
        #pragma unroll 8
        for (int h = 0; h < 256; h++) acc += W1[d * 256 + h] * W2[h * 128 + n];
        W12[idx] = acc;
    } else if (bx == 128) {                 // b1w2 + bias concat
        if (tid < 128) {
            float acc = 0.f;
            for (int h = 0; h < 256; h++) acc += b1[h] * W2[h * 128 + tid];
            b1w2[tid] = acc;
        }
        for (int i = tid; i < 512; i += 256) {
            bias2[i]       = bf[i];
            bias2[512 + i] = bb[i];
        }
    } else if (bx < 145) {                  // idx5 (16 blocks)
        int r = (bx - 129) * 256 + tid;
        if (r < 4096) {
            int lpos = r >> 6, b = r & 63;
            idx5[r]        = b * 64 + lpos;
            idx5[4096 + r] = b * 64 + (63 - lpos);
        }
    } else {                                // transpose4 (1024 blocks)
        int bb2 = bx - 145;
        int mat = bb2 >> 8, blk = bb2 & 255;
        const float* srcs[4] = { s0, s1, s2, s3 };
        const float* in = srcs[mat];
        float* outp = WT + mat * 65536;
        int idx = blk * 256 + tid;
        int g = idx >> 7, k = idx & 127;
        outp[k * 512 + g] = in[idx];
    }
}

// =============== LSTM: 64 CTAs x (dir, 2 batches), early-exit ==============
__global__ __launch_bounds__(512)
void lstm_kernel(const float* __restrict__ xp, const float* __restrict__ WhhT,
                 const int* __restrict__ lengths, float* __restrict__ hfinal)
{
    __shared__ float hs[2][128], cs[2][128];
    __shared__ float red[4][2][512];
    __shared__ float gates[2][512];

    const int tid = threadIdx.x;
    const int dir = blockIdx.x >> 5;
    const int b0  = (blockIdx.x & 31) * 2;
    const int len0 = lengths[b0], len1 = lengths[b0 + 1];
    const int lmax = len0 > len1 ? len0 : len1;
    const int lbeg = (dir == 0) ? 0 : (64 - lmax);
    const int lend = (dir == 0) ? lmax : 64;
    const float4* W4 = (const float4*)(WhhT + dir * 65536);
    const float* xb = xp + (long)dir * 2097152 + (long)b0 * 512;

    if (tid < 256) { ((float*)hs)[tid] = 0.f; ((float*)cs)[tid] = 0.f; }
    __syncthreads();

    const int part = tid >> 7;
    const int q    = tid & 127;
    for (int l = lbeg; l < lend; l++) {
        float a00 = 0.f, a01 = 0.f, a02 = 0.f, a03 = 0.f;
        float a10 = 0.f, a11 = 0.f, a12 = 0.f, a13 = 0.f;
        const int kb = part * 32;
        #pragma unroll 8
        for (int kk = 0; kk < 32; kk++) {
            float4 w = W4[(kb + kk) * 128 + q];
            float h0 = hs[0][kb + kk], h1 = hs[1][kb + kk];
            a00 += w.x * h0; a01 += w.y * h0; a02 += w.z * h0; a03 += w.w * h0;
            a10 += w.x * h1; a11 += w.y * h1; a12 += w.z * h1; a13 += w.w * h1;
        }
        *(float4*)&red[part][0][q * 4] = make_float4(a00, a01, a02, a03);
        *(float4*)&red[part][1][q * 4] = make_float4(a10, a11, a12, a13);
        __syncthreads();
        const float* xl = xb + (long)l * 32768;
        gates[0][tid] = red[0][0][tid] + red[1][0][tid] + red[2][0][tid] + red[3][0][tid] + xl[tid];
        gates[1][tid] = red[0][1][tid] + red[1][1][tid] + red[2][1][tid] + red[3][1][tid] + xl[512 + tid];
        __syncthreads();
        if (tid < 256) {
            int s = tid >> 7, j = tid & 127;
            int ln = s ? len1 : len0;
            bool active = (dir == 0) ? (l < ln) : ((63 - l) < ln);
            if (active) {
                float gi = gates[s][j], gf = gates[s][128 + j];
                float gg = gates[s][256 + j], go = gates[s][384 + j];
                float cn = fsig(gf) * cs[s][j] + fsig(gi) * ftanh(gg);
                cs[s][j] = cn;
                hs[s][j] = fsig(go) * ftanh(cn);
            }
        }
        __syncthreads();
    }
    if (tid < 256) {
        int s = tid >> 7, j = tid & 127;
        hfinal[dir * 8192 + (b0 + s) * 128 + j] = hs[s][j];
    }
}

// =============== final FC ==================================================
__global__ void fc_kernel(const float* __restrict__ hfinal, const float* __restrict__ Wfc,
                          const float* __restrict__ bfc, float* __restrict__ out)
{
    int t = threadIdx.x;
    int b = t >> 2, c = t & 3;
    const float* hf = hfinal + b * 128;
    const float* hb = hfinal + 8192 + b * 128;
    const float* w  = Wfc + c * 256;
    float acc = bfc[c];
    #pragma unroll 8
    for (int j = 0; j < 128; j++) acc += hf[j] * w[j];
    #pragma unroll 8
    for (int j = 0; j < 128; j++) acc += hb[j] * w[128 + j];
    out[b * 4 + c] = acc;
}

// ===========================================================================
extern "C" void kernel_launch(void* const* d_in, const int* in_sizes, int n_in,
                              void* d_out, int out_size)
{
    const float* A     = (const float*)d_in[0];
    const float* X     = (const float*)d_in[1];
    const int*   tok   = (const int*)  d_in[2];
    const int*   len   = (const int*)  d_in[3];
    const float* W1    = (const float*)d_in[4];
    const float* b1    = (const float*)d_in[5];
    const float* W2    = (const float*)d_in[6];
    const float* b2    = (const float*)d_in[7];
    const float* Wih_f = (const float*)d_in[8];
    const float* Whh_f = (const float*)d_in[9];
    const float* b_f   = (const float*)d_in[10];
    const float* Wih_b = (const float*)d_in[11];
    const float* Whh_b = (const float*)d_in[12];
    const float* b_b   = (const float*)d_in[13];
    const float* Wfc   = (const float*)d_in[14];
    const float* bfc   = (const float*)d_in[15];
    float* out = (float*)d_out;

    float *W12, *b1w2, *rowsum, *seqs, *spart, *xp, *WT, *bias2, *hfinal;
    __nv_bfloat16 *Bhi, *Blo, *Bhi2, *Blo2;
    int* idx5;
    cudaGetSymbolAddress((void**)&W12,    g_W12);
    cudaGetSymbolAddress((void**)&b1w2,   g_b1w2);
    cudaGetSymbolAddress((void**)&rowsum, g_rowsum);
    cudaGetSymbolAddress((void**)&Bhi,    g_Bhi);
    cudaGetSymbolAddress((void**)&Blo,    g_Blo);
    cudaGetSymbolAddress((void**)&Bhi2,   g_Bhi2);
    cudaGetSymbolAddress((void**)&Blo2,   g_Blo2);
    cudaGetSymbolAddress((void**)&seqs,   g_seqs);
    cudaGetSymbolAddress((void**)&spart,  g_spart);
    cudaGetSymbolAddress((void**)&xp,     g_xp);
    cudaGetSymbolAddress((void**)&WT,     g_WT);
    cudaGetSymbolAddress((void**)&bias2,  g_bias2);
    cudaGetSymbolAddress((void**)&idx5,   g_idx5);
    cudaGetSymbolAddress((void**)&hfinal, g_hfinal);

    cudaFuncSetAttribute((const void*)gemm_mma_kernel<128, 128>,
                         cudaFuncAttributeMaxDynamicSharedMemorySize, 99328);
    cudaFuncSetAttribute((const void*)gemm_mma_kernel<64, 64>,
                         cudaFuncAttributeMaxDynamicSharedMemorySize, 66560);

    prep_kernel<<<1169, 256>>>(W1, W2, W12, b1, b1w2, idx5,                   // 0
                               Wih_f, Wih_b, Whh_f, Whh_b, WT,
                               b_f, b_b, bias2);
    y0split_kernel<<<dim3(1, 256), 256>>>(X, W12, Bhi, Blo);                  // 1
    gemm_mma_kernel<128, 128><<<dim3(128, 1, 1), 256, 99328>>>(               // 2 GEMM1 fused
        A, Bhi, Blo, nullptr, nullptr, rowsum, Bhi2, Blo2, 0);
    gemm_mma_kernel<64, 64><<<dim3(64, 2, 2), 256, 66560>>>(                  // 3 GEMM2 sK2 (profiled)
        A, Bhi2, Blo2, spart, tok, nullptr, nullptr, nullptr, 524288);
    reduce_seqs_kernel<<<512, 256>>>(spart, tok, rowsum, b2, b1w2, seqs);     // 4
    gemm128_kernel<32, 2><<<dim3(4, 128, 2), 256>>>(seqs, WT, xp,             // 5 xp merged
                                                    4096, 512, 128, idx5, bias2,
                                                    65536, 4096, 2097152, 512);
    lstm_kernel<<<64, 512>>>(xp, WT + 131072, len, hfinal);                   // 6
    fc_kernel<<<1, 256>>>(hfinal, Wfc, bfc, out);                             // 7
}

// round 15
// speedup vs baseline: 1.5008x; 1.5008x over previous
#include <cuda_runtime.h>
#include <cuda_bf16.h>
#include <cstdint>

// ============================ helpers ======================================
__device__ __forceinline__ uint32_t smem_u32(const void* p) {
    uint32_t a;
    asm("{ .reg .u64 t; cvta.to.shared.u64 t, %1; cvt.u32.u64 %0, t; }" : "=r"(a) : "l"(p));
    return a;
}
__device__ __forceinline__ void ldsm_x4(uint32_t* r, uint32_t addr) {
    asm volatile("ldmatrix.sync.aligned.m8n8.x4.shared.b16 {%0,%1,%2,%3}, [%4];"
                 : "=r"(r[0]), "=r"(r[1]), "=r"(r[2]), "=r"(r[3]) : "r"(addr));
}
__device__ __forceinline__ void mma_bf16(float* c, const uint32_t* a, const uint32_t* b) {
    asm volatile("mma.sync.aligned.m16n8k16.row.col.f32.bf16.bf16.f32 "
                 "{%0,%1,%2,%3}, {%4,%5,%6,%7}, {%8,%9}, {%0,%1,%2,%3};"
                 : "+f"(c[0]), "+f"(c[1]), "+f"(c[2]), "+f"(c[3])
                 : "r"(a[0]), "r"(a[1]), "r"(a[2]), "r"(a[3]), "r"(b[0]), "r"(b[1]));
}
__device__ __forceinline__ void cpa16(uint32_t s, const void* g) {
    asm volatile("cp.async.ca.shared.global [%0], [%1], 16;" :: "r"(s), "l"(g));
}
#define CP_COMMIT() asm volatile("cp.async.commit_group;" ::: "memory")
#define CP_WAIT0()  asm volatile("cp.async.wait_group 0;" ::: "memory")
#define SWZ(o) ((o) ^ (((o) >> 3) & 0x70))

__device__ __forceinline__ float fsig(float x) {
    return __fdividef(1.f, 1.f + __expf(-x));
}
__device__ __forceinline__ float ftanh(float x) {
    return 2.f * __fdividef(1.f, 1.f + __expf(-2.f * x)) - 1.f;
}

// ============================ scratch ======================================
__device__ float         g_W12[256 * 128];
__device__ float         g_b1w2[128];
__device__ float         g_Y0[8192 * 128];
__device__ float         g_rowsum[8192];
__device__ __nv_bfloat16 g_Bhi[128 * 8192];
__device__ __nv_bfloat16 g_Blo[128 * 8192];
__device__ __nv_bfloat16 g_Bhi2[128 * 8192];
__device__ __nv_bfloat16 g_Blo2[128 * 8192];
__device__ float         g_seqs[4096 * 128];
__device__ float         g_spart[4 * 4096 * 128];
__device__ float         g_xp[2 * 4096 * 512];
__device__ float         g_WT[4 * 128 * 512];
__device__ int           g_idx5[2 * 4096];
__device__ float         g_hfinal[2 * 64 * 128];

// =================== pipelined mma.sync split-bf16 GEMM ====================
// C[M,128-slice] = gatherRows(A)[M,K-chunk](fp32) @ B[K-chunk,n-slice]
// (B hi/lo [128][8192] bf16). CTA tile 64 x BN, K-tile 64, 256 threads,
// 2-stage cp.async. grid = (M/64 m, 128/BN n, ksplit); C += z*zoff.
// If hi_out != null (BN=128 only): epilogue writes transposed hi/lo bf16.
template<int BN, int NIT>
__global__ __launch_bounds__(256, 1)
void gemm_mma_kernel(const float* __restrict__ A,
                     const __nv_bfloat16* __restrict__ Bhi,
                     const __nv_bfloat16* __restrict__ Blo,
                     float* __restrict__ C,
                     const int* __restrict__ row_idx,
                     float* __restrict__ rowsum_out,
                     __nv_bfloat16* __restrict__ hi_out,
                     __nv_bfloat16* __restrict__ lo_out,
                     long zoff)
{
    constexpr int STAGE   = 16384 + BN * 256;
    constexpr int BLO_OFF = 16384 + BN * 128;
    constexpr int NF      = BN / 32;
    constexpr int PG      = NF / 2;
    constexpr int T       = 256 / BN;
    constexpr int BCH     = 8 / T;

    extern __shared__ char dsm[];
    __shared__ int sidx[64];

    const int tid = threadIdx.x;
    const int w = tid >> 5, l = tid & 31;
    const int m0 = blockIdx.x * 64;
    const int n0 = blockIdx.y * BN;
    const int k0 = blockIdx.z * NIT * 64;
    C += (long)blockIdx.z * zoff;

    if (tid < 64) sidx[tid] = row_idx ? row_idx[m0 + tid] : (m0 + tid);
    __syncthreads();

    const uint32_t dyn = smem_u32(dsm);
    const uint32_t tb0 = (dyn + 1023u) & ~1023u;
    char* const tptr = dsm + (tb0 - dyn);

    const int ar = tid >> 2, aq = tid & 3;
    const float* Ap = A + (long)sidx[ar] * 8192 + k0 + aq * 16;
    const uint32_t aswz0 = SWZ((uint32_t)(ar * 128 + aq * 32));
    const uint32_t aswz1 = SWZ((uint32_t)(ar * 128 + aq * 32 + 16));

    const int rb = tid / T, sub = tid % T;
    const __nv_bfloat16* Bhp = Bhi + (long)(n0 + rb) * 8192 + k0 + sub * (64 / T);
    const __nv_bfloat16* Blp = Blo + (long)(n0 + rb) * 8192 + k0 + sub * (64 / T);
    uint32_t bswz[BCH];
    #pragma unroll
    for (int i = 0; i < BCH; i++)
        bswz[i] = SWZ((uint32_t)(rb * 128 + sub * (128 / T) + i * 16));

    const int mw = (w & 1) * 32, nw = (w >> 1) * (BN / 4);
    uint32_t aLin[2], aMask[2];
    #pragma unroll
    for (int im = 0; im < 2; im++) {
        uint32_t lin = (uint32_t)((mw + 16 * im + (l & 15)) * 128 + (l >> 4) * 16);
        aLin[im] = lin;
        aMask[im] = (lin >> 3) & 0x70;
    }
    uint32_t bLin[PG], bMask[PG];
    #pragma unroll
    for (int pg = 0; pg < PG; pg++) {
        uint32_t n = (uint32_t)(nw + (pg * 2 + (l >> 4)) * 8 + (l & 7));
        uint32_t lin = n * 128 + ((l >> 3) & 1) * 16;
        bLin[pg] = lin;
        bMask[pg] = (lin >> 3) & 0x70;
    }

    float acc[2][NF][4];
    #pragma unroll
    for (int im = 0; im < 2; im++)
        #pragma unroll
        for (int jn = 0; jn < NF; jn++)
            #pragma unroll
            for (int e = 0; e < 4; e++) acc[im][jn][e] = 0.f;

    float racc = 0.f;
    const bool do_rs = (rowsum_out != nullptr) && (blockIdx.y == 0);

    float4 av[4];
    #pragma unroll
    for (int i = 0; i < 4; i++) av[i] = *(const float4*)(Ap + i * 4);
    #pragma unroll
    for (int i = 0; i < BCH; i++) {
        cpa16(tb0 + 16384   + bswz[i], (const char*)Bhp + i * 16);
        cpa16(tb0 + BLO_OFF + bswz[i], (const char*)Blp + i * 16);
    }
    CP_COMMIT();

    for (int it = 0; it < NIT; it++) {
        const int s = it & 1;
        char* const sp = tptr + s * STAGE;

        {
            float vv[16] = { av[0].x, av[0].y, av[0].z, av[0].w,
                             av[1].x, av[1].y, av[1].z, av[1].w,
                             av[2].x, av[2].y, av[2].z, av[2].w,
                             av[3].x, av[3].y, av[3].z, av[3].w };
            uint32_t hu[8], lu[8];
            #pragma unroll
            for (int p = 0; p < 8; p++) {
                float x = vv[2 * p], y = vv[2 * p + 1];
                __nv_bfloat16 hx = __float2bfloat16(x);
                __nv_bfloat16 hy = __float2bfloat16(y);
                __nv_bfloat16 lx = __float2bfloat16(x - __bfloat162float(hx));
                __nv_bfloat16 ly = __float2bfloat16(y - __bfloat162float(hy));
                hu[p] = (uint32_t)__bfloat16_as_ushort(hx) |
                        ((uint32_t)__bfloat16_as_ushort(hy) << 16);
                lu[p] = (uint32_t)__bfloat16_as_ushort(lx) |
                        ((uint32_t)__bfloat16_as_ushort(ly) << 16);
            }
            if (do_rs) {
                float sacc = 0.f;
                #pragma unroll
                for (int p = 0; p < 16; p++) sacc += vv[p];
                racc += sacc;
            }
            *(uint4*)(sp +        aswz0) = make_uint4(hu[0], hu[1], hu[2], hu[3]);
            *(uint4*)(sp +        aswz1) = make_uint4(hu[4], hu[5], hu[6], hu[7]);
            *(uint4*)(sp + 8192 + aswz0) = make_uint4(lu[0], lu[1], lu[2], lu[3]);
            *(uint4*)(sp + 8192 + aswz1) = make_uint4(lu[4], lu[5], lu[6], lu[7]);
        }
        if (it + 1 < NIT) {
            const int kt = (it + 1) * 64;
            #pragma unroll
            for (int i = 0; i < 4; i++) av[i] = *(const float4*)(Ap + kt + i * 4);
        }

        CP_WAIT0();
        __syncthreads();

        if (it + 1 < NIT) {
            const int kt = (it + 1) * 64;
            const uint32_t db = tb0 + (s ^ 1) * STAGE;
            #pragma unroll
            for (int i = 0; i < BCH; i++) {
                cpa16(db + 16384   + bswz[i], (const char*)(Bhp + kt) + i * 16);
                cpa16(db + BLO_OFF + bswz[i], (const char*)(Blp + kt) + i * 16);
            }
            CP_COMMIT();
        }

        const uint32_t cb = tb0 + s * STAGE;
        #pragma unroll
        for (int ks = 0; ks < 4; ks++) {
            const uint32_t kb = ks * 32;
            uint32_t ah[2][4], al[2][4], bh[NF][2], bl[NF][2];
            #pragma unroll
            for (int im = 0; im < 2; im++) {
                uint32_t off = (aLin[im] + kb) ^ aMask[im];
                ldsm_x4(ah[im], cb + off);
                ldsm_x4(al[im], cb + 8192 + off);
            }
            #pragma unroll
            for (int pg = 0; pg < PG; pg++) {
                uint32_t off = (bLin[pg] + kb) ^ bMask[pg];
                uint32_t t4[4];
                ldsm_x4(t4, cb + 16384 + off);
                bh[pg * 2][0] = t4[0]; bh[pg * 2][1] = t4[1];
                bh[pg * 2 + 1][0] = t4[2]; bh[pg * 2 + 1][1] = t4[3];
                ldsm_x4(t4, cb + BLO_OFF + off);
                bl[pg * 2][0] = t4[0]; bl[pg * 2][1] = t4[1];
                bl[pg * 2 + 1][0] = t4[2]; bl[pg * 2 + 1][1] = t4[3];
            }
            #pragma unroll
            for (int im = 0; im < 2; im++)
                #pragma unroll
                for (int jn = 0; jn < NF; jn++) {
                    mma_bf16(acc[im][jn], ah[im], bh[jn]);
                    mma_bf16(acc[im][jn], ah[im], bl[jn]);
                    mma_bf16(acc[im][jn], al[im], bh[jn]);
                }
        }
    }

    if (do_rs) {
        racc += __shfl_xor_sync(0xffffffffu, racc, 1);
        racc += __shfl_xor_sync(0xffffffffu, racc, 2);
        if (aq == 0) rowsum_out[m0 + ar] = racc;
    }

    const int g = l >> 2, q = l & 3;
    if (BN == 128 && hi_out) {
        __syncthreads();
        #pragma unroll
        for (int im = 0; im < 2; im++) {
            const int rl0 = mw + 16 * im + g;
            const int rl1 = rl0 + 8;
            #pragma unroll
            for (int jn = 0; jn < NF; jn++) {
                const int col = nw + 8 * jn + 2 * q;
                float vs[4] = { acc[im][jn][0], acc[im][jn][1],
                                acc[im][jn][2], acc[im][jn][3] };
                int rr[4] = { rl0, rl0, rl1, rl1 };
                int cc[4] = { col, col + 1, col, col + 1 };
                #pragma unroll
                for (int e = 0; e < 4; e++) {
                    __nv_bfloat16 h = __float2bfloat16(vs[e]);
                    __nv_bfloat16 lo = __float2bfloat16(vs[e] - __bfloat162float(h));
                    *(__nv_bfloat16*)(tptr + cc[e] * 144 + rr[e] * 2) = h;
                    *(__nv_bfloat16*)(tptr + 18432 + cc[e] * 144 + rr[e] * 2) = lo;
                }
            }
        }
        __syncthreads();
        #pragma unroll
        for (int i = 0; i < 4; i++) {
            int u = tid + 256 * i;
            int n = u >> 3, c = u & 7;
            *(uint4*)(hi_out + (long)n * 8192 + m0 + c * 8) =
                *(const uint4*)(tptr + n * 144 + c * 16);
            *(uint4*)(lo_out + (long)n * 8192 + m0 + c * 8) =
                *(const uint4*)(tptr + 18432 + n * 144 + c * 16);
        }
    } else {
        #pragma unroll
        for (int im = 0; im < 2; im++) {
            const int rl0 = mw + 16 * im + g;
            const int rl1 = rl0 + 8;
            #pragma unroll
            for (int jn = 0; jn < NF; jn++) {
                const int col = n0 + nw + 8 * jn + 2 * q;
                float* p0 = C + (long)(m0 + rl0) * 128 + col;
                float* p1 = C + (long)(m0 + rl1) * 128 + col;
                *(float2*)p0 = make_float2(acc[im][jn][0], acc[im][jn][1]);
                *(float2*)p1 = make_float2(acc[im][jn][2], acc[im][jn][3]);
            }
        }
    }
}

// =============== split-K(4) reduce + bias for seqs =========================
__global__ __launch_bounds__(256)
void reduce_seqs_kernel(const float* __restrict__ part, const int* __restrict__ tok,
                        const float* __restrict__ rowsum, const float* __restrict__ b2,
                        const float* __restrict__ b1w2, float* __restrict__ seqs)
{
    int f = blockIdx.x * 256 + threadIdx.x;      // 131072 float4s
    int r = f >> 5, c4 = f & 31;
    float4 a = ((const float4*)part)[f];
    float4 b = ((const float4*)(part + 524288))[f];
    float4 c = ((const float4*)(part + 1048576))[f];
    float4 d = ((const float4*)(part + 1572864))[f];
    float rs = rowsum[tok[r]];
    float4 bb = ((const float4*)b2)[c4];
    float4 vv = ((const float4*)b1w2)[c4];
    float4 o;
    o.x = a.x + b.x + c.x + d.x + bb.x + rs * vv.x;
    o.y = a.y + b.y + c.y + d.y + bb.y + rs * vv.y;
    o.z = a.z + b.z + c.z + d.z + bb.z + rs * vv.z;
    o.w = a.w + b.w + c.w + d.w + bb.w + rs * vv.w;
    ((float4*)seqs)[f] = o;
}

// =============== fp32 tiled GEMM (Y0, xp) ==================================
template<int BM, int MR>
__launch_bounds__(256)
__global__ void gemm128_kernel(const float* __restrict__ A, const float* __restrict__ B,
                               float* __restrict__ C, int M, int N, int K,
                               const int* __restrict__ row_idx,
                               const float* __restrict__ bias)
{
    constexpr int BK  = 16;
    constexpr int PAD = BM + 4;
    __shared__ float As[BK][PAD];
    __shared__ float Bs[BK][128];
    __shared__ int   sidx[BM];

    const int tid = threadIdx.x;
    const int tx = tid & 15, ty = tid >> 4;
    const int m0 = blockIdx.y * BM, n0 = blockIdx.x * 128;

    if (row_idx && tid < BM) sidx[tid] = row_idx[m0 + tid];
    __syncthreads();

    const int aThreads = BM * 4;
    const int lr = tid >> 2, lc4 = tid & 3;
    const float* Ap = nullptr;
    if (tid < aThreads) {
        int arr = row_idx ? sidx[lr] : (m0 + lr);
        Ap = A + (long)arr * K + lc4 * 4;
    }
    const int kb0 = tid >> 5, kc0 = tid & 31;
    const float* Bp0 = B + (long)kb0 * N + n0 + kc0 * 4;
    const float* Bp1 = B + (long)(kb0 + 8) * N + n0 + kc0 * 4;

    float acc[MR][8];
    #pragma unroll
    for (int i = 0; i < MR; i++)
        #pragma unroll
        for (int j = 0; j < 8; j++) acc[i][j] = 0.f;

    float4 av = make_float4(0.f, 0.f, 0.f, 0.f);
    if (tid < aThreads) av = *(const float4*)Ap;
    float4 bv0 = *(const float4*)Bp0;
    float4 bv1 = *(const float4*)Bp1;

    for (int kt = 0; kt < K; kt += BK) {
        __syncthreads();
        if (tid < aThreads) {
            As[lc4 * 4 + 0][lr] = av.x; As[lc4 * 4 + 1][lr] = av.y;
            As[lc4 * 4 + 2][lr] = av.z; As[lc4 * 4 + 3][lr] = av.w;
        }
        *(float4*)&Bs[kb0][kc0 * 4]     = bv0;
        *(float4*)&Bs[kb0 + 8][kc0 * 4] = bv1;
        __syncthreads();
        if (kt + BK < K) {
            if (tid < aThreads) av = *(const float4*)(Ap + kt + BK);
            bv0 = *(const float4*)(Bp0 + (long)(kt + BK) * N);
            bv1 = *(const float4*)(Bp1 + (long)(kt + BK) * N);
        }
        #pragma unroll
        for (int k = 0; k < BK; k++) {
            float a[MR];
            #pragma unroll
            for (int i = 0; i < MR; i++) a[i] = As[k][ty * MR + i];
            float4 b0 = *(const float4*)&Bs[k][tx * 8];
            float4 b1 = *(const float4*)&Bs[k][tx * 8 + 4];
            #pragma unroll
            for (int i = 0; i < MR; i++) {
                acc[i][0] += a[i] * b0.x; acc[i][1] += a[i] * b0.y;
                acc[i][2] += a[i] * b0.z; acc[i][3] += a[i] * b0.w;
                acc[i][4] += a[i] * b1.x; acc[i][5] += a[i] * b1.y;
                acc[i][6] += a[i] * b1.z; acc[i][7] += a[i] * b1.w;
            }
        }
    }
    float addc[8];
    #pragma unroll
    for (int j = 0; j < 8; j++) addc[j] = bias ? bias[n0 + tx * 8 + j] : 0.f;
    #pragma unroll
    for (int i = 0; i < MR; i++) {
        int rr = ty * MR + i;
        float* crow = C + (long)(m0 + rr) * N + n0 + tx * 8;
        *(float4*)(crow)     = make_float4(acc[i][0] + addc[0], acc[i][1] + addc[1],
                                           acc[i][2] + addc[2], acc[i][3] + addc[3]);
        *(float4*)(crow + 4) = make_float4(acc[i][4] + addc[4], acc[i][5] + addc[5],
                                           acc[i][6] + addc[6], acc[i][7] + addc[7]);
    }
}

// =============== prep kernels ==============================================
__global__ void w12_kernel(const float* __restrict__ W1, const float* __restrict__ W2,
                           float* __restrict__ W12)
{
    int idx = blockIdx.x * 256 + threadIdx.x;
    if (idx < 256 * 128) {
        int d = idx >> 7, n = idx & 127;
        float acc = 0.f;
        #pragma unroll 8
        for (int h = 0; h < 256; h++) acc += W1[d * 256 + h] * W2[h * 128 + n];
        W12[idx] = acc;
    }
}
__global__ void b1w2_kernel(const float* __restrict__ b1, const float* __restrict__ W2,
                            float* __restrict__ out)
{
    int n = threadIdx.x;
    float acc = 0.f;
    for (int h = 0; h < 256; h++) acc += b1[h] * W2[h * 128 + n];
    out[n] = acc;
}
__global__ void transpose4_kernel(const float* __restrict__ s0, const float* __restrict__ s1,
                                  const float* __restrict__ s2, const float* __restrict__ s3,
                                  float* __restrict__ WT)
{
    const float* srcs[4] = { s0, s1, s2, s3 };
    const float* in = srcs[blockIdx.y];
    float* out = WT + blockIdx.y * 65536;
    int idx = blockIdx.x * 256 + threadIdx.x;
    int g = idx >> 7, k = idx & 127;
    out[k * 512 + g] = in[idx];
}
__global__ void idx5_kernel(int* __restrict__ idx)
{
    int r = blockIdx.x * 256 + threadIdx.x;
    if (r < 4096) {
        int l = r >> 6, b = r & 63;
        idx[r]        = b * 64 + l;
        idx[4096 + r] = b * 64 + (63 - l);
    }
}
// [8192][128] fp32 -> hi/lo [128][8192] bf16 (Y0 path)
__global__ __launch_bounds__(256)
void conv_tsplit_kernel(const float* __restrict__ in,
                        __nv_bfloat16* __restrict__ hi,
                        __nv_bfloat16* __restrict__ lo)
{
    __shared__ __nv_bfloat16 sh[128][72];
    __shared__ __nv_bfloat16 sl[128][72];
    const int tid = threadIdx.x;
    const int m0 = blockIdx.x * 64;

    #pragma unroll
    for (int i = 0; i < 8; i++) {
        int f = tid + 256 * i;
        int m = f >> 5, c4 = f & 31;
        float4 v = *(const float4*)(in + (long)(m0 + m) * 128 + c4 * 4);
        float vv[4] = { v.x, v.y, v.z, v.w };
        #pragma unroll
        for (int e = 0; e < 4; e++) {
            int n = c4 * 4 + e;
            __nv_bfloat16 h = __float2bfloat16(vv[e]);
            sh[n][m] = h;
            sl[n][m] = __float2bfloat16(vv[e] - __bfloat162float(h));
        }
    }
    __syncthreads();
    #pragma unroll
    for (int i = 0; i < 4; i++) {
        int u = tid + 256 * i;
        int n = u >> 3, c = u & 7;
        *(uint4*)(hi + (long)n * 8192 + m0 + c * 8) = *(const uint4*)&sh[n][c * 8];
        *(uint4*)(lo + (long)n * 8192 + m0 + c * 8) = *(const uint4*)&sl[n][c * 8];
    }
}

// =============== LSTM: 64 CTAs x (dir, 2 batches), early-exit ==============
__global__ __launch_bounds__(512)
void lstm_kernel(const float* __restrict__ xp, const float* __restrict__ WhhT,
                 const int* __restrict__ lengths, float* __restrict__ hfinal)
{
    __shared__ float hs[2][128], cs[2][128];
    __shared__ float red[4][2][512];
    __shared__ float gates[2][512];

    const int tid = threadIdx.x;
    const int dir = blockIdx.x >> 5;
    const int b0  = (blockIdx.x & 31) * 2;
    const int len0 = lengths[b0], len1 = lengths[b0 + 1];
    const int lmax = len0 > len1 ? len0 : len1;
    const int lbeg = (dir == 0) ? 0 : (64 - lmax);
    const int lend = (dir == 0) ? lmax : 64;
    const float4* W4 = (const float4*)(WhhT + dir * 65536);
    const float* xb = xp + (long)dir * 2097152 + (long)b0 * 512;

    if (tid < 256) { ((float*)hs)[tid] = 0.f; ((float*)cs)[tid] = 0.f; }
    __syncthreads();

    const int part = tid >> 7;
    const int q    = tid & 127;
    for (int l = lbeg; l < lend; l++) {
        float a00 = 0.f, a01 = 0.f, a02 = 0.f, a03 = 0.f;
        float a10 = 0.f, a11 = 0.f, a12 = 0.f, a13 = 0.f;
        const int kb = part * 32;
        #pragma unroll 8
        for (int kk = 0; kk < 32; kk++) {
            float4 w = W4[(kb + kk) * 128 + q];
            float h0 = hs[0][kb + kk], h1 = hs[1][kb + kk];
            a00 += w.x * h0; a01 += w.y * h0; a02 += w.z * h0; a03 += w.w * h0;
            a10 += w.x * h1; a11 += w.y * h1; a12 += w.z * h1; a13 += w.w * h1;
        }
        *(float4*)&red[part][0][q * 4] = make_float4(a00, a01, a02, a03);
        *(float4*)&red[part][1][q * 4] = make_float4(a10, a11, a12, a13);
        __syncthreads();
        const float* xl = xb + (long)l * 32768;
        gates[0][tid] = red[0][0][tid] + red[1][0][tid] + red[2][0][tid] + red[3][0][tid] + xl[tid];
        gates[1][tid] = red[0][1][tid] + red[1][1][tid] + red[2][1][tid] + red[3][1][tid] + xl[512 + tid];
        __syncthreads();
        if (tid < 256) {
            int s = tid >> 7, j = tid & 127;
            int ln = s ? len1 : len0;
            bool active = (dir == 0) ? (l < ln) : ((63 - l) < ln);
            if (active) {
                float gi = gates[s][j], gf = gates[s][128 + j];
                float gg = gates[s][256 + j], go = gates[s][384 + j];
                float cn = fsig(gf) * cs[s][j] + fsig(gi) * ftanh(gg);
                cs[s][j] = cn;
                hs[s][j] = fsig(go) * ftanh(cn);
            }
        }
        __syncthreads();
    }
    if (tid < 256) {
        int s = tid >> 7, j = tid & 127;
        hfinal[dir * 8192 + (b0 + s) * 128 + j] = hs[s][j];
    }
}

// =============== final FC ==================================================
__global__ void fc_kernel(const float* __restrict__ hfinal, const float* __restrict__ Wfc,
                          const float* __restrict__ bfc, float* __restrict__ out)
{
    int t = threadIdx.x;
    int b = t >> 2, c = t & 3;
    const float* hf = hfinal + b * 128;
    const float* hb = hfinal + 8192 + b * 128;
    const float* w  = Wfc + c * 256;
    float acc = bfc[c];
    #pragma unroll 8
    for (int j = 0; j < 128; j++) acc += hf[j] * w[j];
    #pragma unroll 8
    for (int j = 0; j < 128; j++) acc += hb[j] * w[128 + j];
    out[b * 4 + c] = acc;
}

// ===========================================================================
extern "C" void kernel_launch(void* const* d_in, const int* in_sizes, int n_in,
                              void* d_out, int out_size)
{
    const float* A     = (const float*)d_in[0];
    const float* X     = (const float*)d_in[1];
    const int*   tok   = (const int*)  d_in[2];
    const int*   len   = (const int*)  d_in[3];
    const float* W1    = (const float*)d_in[4];
    const float* b1    = (const float*)d_in[5];
    const float* W2    = (const float*)d_in[6];
    const float* b2    = (const float*)d_in[7];
    const float* Wih_f = (const float*)d_in[8];
    const float* Whh_f = (const float*)d_in[9];
    const float* b_f   = (const float*)d_in[10];
    const float* Wih_b = (const float*)d_in[11];
    const float* Whh_b = (const float*)d_in[12];
    const float* b_b   = (const float*)d_in[13];
    const float* Wfc   = (const float*)d_in[14];
    const float* bfc   = (const float*)d_in[15];
    float* out = (float*)d_out;

    float *W12, *b1w2, *Y0, *rowsum, *seqs, *spart, *xp, *WT, *hfinal;
    __nv_bfloat16 *Bhi, *Blo, *Bhi2, *Blo2;
    int* idx5;
    cudaGetSymbolAddress((void**)&W12,    g_W12);
    cudaGetSymbolAddress((void**)&b1w2,   g_b1w2);
    cudaGetSymbolAddress((void**)&Y0,     g_Y0);
    cudaGetSymbolAddress((void**)&rowsum, g_rowsum);
    cudaGetSymbolAddress((void**)&Bhi,    g_Bhi);
    cudaGetSymbolAddress((void**)&Blo,    g_Blo);
    cudaGetSymbolAddress((void**)&Bhi2,   g_Bhi2);
    cudaGetSymbolAddress((void**)&Blo2,   g_Blo2);
    cudaGetSymbolAddress((void**)&seqs,   g_seqs);
    cudaGetSymbolAddress((void**)&spart,  g_spart);
    cudaGetSymbolAddress((void**)&xp,     g_xp);
    cudaGetSymbolAddress((void**)&WT,     g_WT);
    cudaGetSymbolAddress((void**)&idx5,   g_idx5);
    cudaGetSymbolAddress((void**)&hfinal, g_hfinal);

    cudaFuncSetAttribute((const void*)gemm_mma_kernel<128, 128>,
                         cudaFuncAttributeMaxDynamicSharedMemorySize, 99328);
    cudaFuncSetAttribute((const void*)gemm_mma_kernel<128, 32>,
                         cudaFuncAttributeMaxDynamicSharedMemorySize, 99328);

    w12_kernel<<<128, 256>>>(W1, W2, W12);                                    // 0
    gemm128_kernel<32, 2><<<dim3(1, 256), 256>>>(X, W12, Y0,                  // 1
                                                 8192, 128, 256, nullptr, nullptr);
    conv_tsplit_kernel<<<128, 256>>>(Y0, Bhi, Blo);                           // 2
    gemm_mma_kernel<128, 128><<<dim3(128, 1, 1), 256, 99328>>>(               // 3 GEMM1 fused
        A, Bhi, Blo, nullptr, nullptr, rowsum, Bhi2, Blo2, 0);
    b1w2_kernel<<<1, 128>>>(b1, W2, b1w2);                                    // 4
    idx5_kernel<<<16, 256>>>(idx5);                                           // 5
    gemm_mma_kernel<128, 32><<<dim3(64, 1, 4), 256, 99328>>>(                 // 6 GEMM2 sK4
        A, Bhi2, Blo2, spart, tok, nullptr, nullptr, nullptr, 524288);
    reduce_seqs_kernel<<<512, 256>>>(spart, tok, rowsum, b2, b1w2, seqs);     // 7
    transpose4_kernel<<<dim3(256, 4), 256>>>(Wih_f, Wih_b, Whh_f, Whh_b, WT); // 8
    gemm128_kernel<32, 2><<<dim3(4, 128), 256>>>(seqs, WT, xp,                // 9
                                                 4096, 512, 128, idx5, b_f);
    gemm128_kernel<32, 2><<<dim3(4, 128), 256>>>(seqs, WT + 65536,            // 10
                                                 xp + 2097152, 4096, 512, 128,
                                                 idx5 + 4096, b_b);
    lstm_kernel<<<64, 512>>>(xp, WT + 131072, len, hfinal);                   // 11
    fc_kernel<<<1, 256>>>(hfinal, Wfc, bfc, out);                             // 12
}